// round 2
// baseline (speedup 1.0000x reference)
#include <cuda_runtime.h>
#include <math.h>

#define Bq 512
#define Sq 4096
#define Dq 128
#define Vq 6
#define Kq 409

// Precomputed per-token-value tables
__device__ float g_score[Vq];
__device__ float g_att[Vq * Dq];
__device__ int   g_order[Vq];

// ---------------------------------------------------------------------------
// Kernel 1: tiny precompute — 6 token values through importance MLP and
// attention approximator. One block, 128 threads.
// ---------------------------------------------------------------------------
__global__ void precompute_kernel(
    const float* __restrict__ emb,
    const float* __restrict__ W1, const float* __restrict__ b1,
    const float* __restrict__ W2, const float* __restrict__ b2,
    const float* __restrict__ W3, const float* __restrict__ b3,
    const float* __restrict__ A1, const float* __restrict__ a1,
    const float* __restrict__ A2, const float* __restrict__ a2)
{
    __shared__ float e[Dq];
    __shared__ float h1[64];
    __shared__ float h2[32];
    __shared__ float g1[64];
    const int t = threadIdx.x;  // 128 threads

    for (int v = 0; v < Vq; v++) {
        if (t < Dq) e[t] = emb[v * Dq + t];
        __syncthreads();
        if (t < 64) {
            float s = b1[t];
            float sa = a1[t];
            #pragma unroll 4
            for (int i = 0; i < Dq; i++) {
                s  += e[i] * W1[i * 64 + t];
                sa += e[i] * A1[i * 64 + t];
            }
            h1[t] = fmaxf(s, 0.f);
            g1[t] = fmaxf(sa, 0.f);
        }
        __syncthreads();
        if (t < 32) {
            float s = b2[t];
            #pragma unroll 4
            for (int i = 0; i < 64; i++) s += h1[i] * W2[i * 32 + t];
            h2[t] = fmaxf(s, 0.f);
        }
        __syncthreads();
        if (t == 0) {
            float z = b3[0];
            for (int i = 0; i < 32; i++) z += h2[i] * W3[i];
            g_score[v] = 1.f / (1.f + expf(-z));
        }
        if (t < Dq) {
            float s = a2[t];
            #pragma unroll 4
            for (int j = 0; j < 64; j++) s += g1[j] * A2[j * Dq + t];
            g_att[v * Dq + t] = s;
        }
        __syncthreads();
    }

    if (t == 0) {
        // stable descending selection sort of 6 scores (ties -> lower index,
        // matching jax.lax.top_k stability)
        bool used[Vq];
        for (int v = 0; v < Vq; v++) used[v] = false;
        for (int g = 0; g < Vq; g++) {
            int best = -1; float bs = -1e30f;
            for (int v = 0; v < Vq; v++)
                if (!used[v] && g_score[v] > bs) { bs = g_score[v]; best = v; }
            used[best] = true;
            g_order[g] = best;
        }
    }
}

// ---------------------------------------------------------------------------
// Kernel 2: one CTA per batch row. 256 threads, 16 tokens/thread.
//   pass 1: vectorized load of x row, write final_scores via LUT, local hist
//   scan  : 6 warps each exclusive-scan one token's 256 per-thread counts
//   pass 2: compaction -> top_idx (group order = score descending, stable)
//   epilogue: pooled = sum take[v]*att[v]/K; classifier MLP -> pred[b]
// ---------------------------------------------------------------------------
__global__ __launch_bounds__(256) void main_kernel(
    const int* __restrict__ x,
    const float* __restrict__ C1, const float* __restrict__ c1,
    const float* __restrict__ C2, const float* __restrict__ c2,
    float* __restrict__ out)
{
    const int b = blockIdx.x;
    const int t = threadIdx.x;  // 256 threads

    __shared__ int   cnt[Vq][256];
    __shared__ float score_sm[Vq];
    __shared__ int   take_sm[Vq], off_sm[Vq], tot_sm[Vq];
    __shared__ float pooled[Dq];
    __shared__ float hcls[64];

    if (t < Vq) score_sm[t] = g_score[t];
    __syncthreads();

    const int4* xb = (const int4*)(x + (size_t)b * Sq);
    float* fs = out + Bq + (size_t)Bq * Kq + (size_t)b * Sq;

    int vals[16];
    int lc[Vq];
    #pragma unroll
    for (int v = 0; v < Vq; v++) lc[v] = 0;

    #pragma unroll
    for (int i = 0; i < 4; i++) {
        int4 p = xb[t * 4 + i];
        vals[i * 4 + 0] = p.x; vals[i * 4 + 1] = p.y;
        vals[i * 4 + 2] = p.z; vals[i * 4 + 3] = p.w;
        float4 f;
        f.x = score_sm[p.x]; f.y = score_sm[p.y];
        f.z = score_sm[p.z]; f.w = score_sm[p.w];
        ((float4*)fs)[t * 4 + i] = f;
        #pragma unroll
        for (int j = 0; j < 4; j++) {
            int vv = vals[i * 4 + j];
            #pragma unroll
            for (int v = 0; v < Vq; v++) lc[v] += (vv == v);
        }
    }
    #pragma unroll
    for (int v = 0; v < Vq; v++) cnt[v][t] = lc[v];
    __syncthreads();

    // exclusive scan per token value: warp v scans cnt[v][0..255]
    const int wid = t >> 5, lane = t & 31;
    if (wid < Vq) {
        const int v = wid;
        int loc[8], s = 0;
        #pragma unroll
        for (int i = 0; i < 8; i++) { loc[i] = s; s += cnt[v][lane * 8 + i]; }
        int run = s;
        #pragma unroll
        for (int d = 1; d < 32; d <<= 1) {
            int o = __shfl_up_sync(0xffffffff, run, d);
            if (lane >= d) run += o;
        }
        const int excl = run - s;
        #pragma unroll
        for (int i = 0; i < 8; i++) cnt[v][lane * 8 + i] = excl + loc[i];
        if (lane == 31) tot_sm[v] = run;
    }
    __syncthreads();

    if (t == 0) {
        int rem = Kq, off = 0;
        for (int g = 0; g < Vq; g++) {
            int v = g_order[g];
            int tk = min(tot_sm[v], rem);
            take_sm[v] = tk; off_sm[v] = off;
            off += tk; rem -= tk;
        }
    }
    __syncthreads();

    // pass 2: compaction writes of selected indices (as float, per out dtype)
    int ctr[Vq];
    #pragma unroll
    for (int v = 0; v < Vq; v++) ctr[v] = cnt[v][t];
    float* oidx = out + Bq + (size_t)b * Kq;
    #pragma unroll
    for (int i = 0; i < 16; i++) {
        const int vv = vals[i];
        int rank = 0, tk = 0, off = 0;
        #pragma unroll
        for (int v = 0; v < Vq; v++)
            if (vv == v) { rank = ctr[v]++; tk = take_sm[v]; off = off_sm[v]; }
        if (rank < tk) oidx[off + rank] = (float)(t * 16 + i);
    }

    // epilogue: pooled mean over selected attended rows, then classifier
    if (t < Dq) {
        float s = 0.f;
        #pragma unroll
        for (int v = 0; v < Vq; v++)
            s += (float)take_sm[v] * g_att[v * Dq + t];
        pooled[t] = s / (float)Kq;
    }
    __syncthreads();
    if (t < 64) {
        float s = c1[t];
        #pragma unroll 4
        for (int i = 0; i < Dq; i++) s += pooled[i] * C1[i * 64 + t];
        hcls[t] = fmaxf(s, 0.f);
    }
    __syncthreads();
    if (t == 0) {
        float z = c2[0];
        for (int i = 0; i < 64; i++) z += hcls[i] * C2[i];
        out[b] = 1.f / (1.f + expf(-z));
    }
}

extern "C" void kernel_launch(void* const* d_in, const int* in_sizes, int n_in,
                              void* d_out, int out_size) {
    const int*   x   = (const int*)d_in[0];
    const float* emb = (const float*)d_in[1];
    const float* W1  = (const float*)d_in[2];
    const float* b1  = (const float*)d_in[3];
    const float* W2  = (const float*)d_in[4];
    const float* b2  = (const float*)d_in[5];
    const float* W3  = (const float*)d_in[6];
    const float* b3  = (const float*)d_in[7];
    const float* A1  = (const float*)d_in[8];
    const float* a1  = (const float*)d_in[9];
    const float* A2  = (const float*)d_in[10];
    const float* a2  = (const float*)d_in[11];
    const float* C1  = (const float*)d_in[12];
    const float* c1  = (const float*)d_in[13];
    const float* C2  = (const float*)d_in[14];
    const float* c2  = (const float*)d_in[15];
    float* out = (float*)d_out;

    precompute_kernel<<<1, 128>>>(emb, W1, b1, W2, b2, W3, b3, A1, a1, A2, a2);
    main_kernel<<<Bq, 256>>>(x, C1, c1, C2, c2, out);
}

// round 3
// speedup vs baseline: 1.6283x; 1.6283x over previous
#include <cuda_runtime.h>
#include <math.h>

#define Bq 512
#define Sq 4096
#define Dq 128
#define Vq 6
#define Kq 409

// Precomputed per-token-value tables
__device__ float g_score[Vq];
__device__ float g_att[Vq * Dq];

// ---------------------------------------------------------------------------
// Kernel 1: precompute — 6 blocks, one per token value. 128 threads each.
// All 6 MLPs run concurrently; weight loads unrolled for MLP.
// ---------------------------------------------------------------------------
__global__ __launch_bounds__(128) void precompute_kernel(
    const float* __restrict__ emb,
    const float* __restrict__ W1, const float* __restrict__ b1,
    const float* __restrict__ W2, const float* __restrict__ b2,
    const float* __restrict__ W3, const float* __restrict__ b3,
    const float* __restrict__ A1, const float* __restrict__ a1,
    const float* __restrict__ A2, const float* __restrict__ a2)
{
    const int v = blockIdx.x;
    const int t = threadIdx.x;  // 128 threads
    __shared__ float e[Dq];
    __shared__ float h1[64];
    __shared__ float g1[64];
    __shared__ float h2[32];

    if (t < Dq) e[t] = emb[v * Dq + t];
    __syncthreads();

    if (t < 64) {
        float s  = b1[t];
        float sa = a1[t];
        #pragma unroll 8
        for (int i = 0; i < Dq; i++) {
            s  += e[i] * W1[i * 64 + t];
            sa += e[i] * A1[i * 64 + t];
        }
        h1[t] = fmaxf(s, 0.f);
        g1[t] = fmaxf(sa, 0.f);
    }
    __syncthreads();

    if (t < 32) {
        float s = b2[t];
        #pragma unroll 8
        for (int i = 0; i < 64; i++) s += h1[i] * W2[i * 32 + t];
        h2[t] = fmaxf(s, 0.f);
    }
    __syncthreads();

    if (t < 32) {
        float z = h2[t] * W3[t];
        #pragma unroll
        for (int d = 16; d >= 1; d >>= 1) z += __shfl_xor_sync(0xffffffff, z, d);
        if (t == 0) g_score[v] = 1.f / (1.f + expf(-(z + b3[0])));
    }
    if (t < Dq) {
        float s = a2[t];
        #pragma unroll 8
        for (int j = 0; j < 64; j++) s += g1[j] * A2[j * Dq + t];
        g_att[v * Dq + t] = s;
    }
}

// ---------------------------------------------------------------------------
// Kernel 2: one CTA per batch row. 256 threads, 16 tokens/thread.
// ---------------------------------------------------------------------------
__global__ __launch_bounds__(256) void main_kernel(
    const int* __restrict__ x,
    const float* __restrict__ C1, const float* __restrict__ c1,
    const float* __restrict__ C2, const float* __restrict__ c2,
    float* __restrict__ out)
{
    const int b = blockIdx.x;
    const int t = threadIdx.x;  // 256 threads

    __shared__ int   cnt[Vq][256];
    __shared__ float score_sm[Vq];
    __shared__ int   take_sm[Vq], off_sm[Vq], tot_sm[Vq];
    __shared__ float sh_idx[Kq];
    __shared__ float pooled[Dq];
    __shared__ float hcls[64];

    if (t < Vq) score_sm[t] = g_score[t];
    __syncthreads();

    const int4* xb = (const int4*)(x + (size_t)b * Sq);
    float* fs = out + Bq + (size_t)Bq * Kq + (size_t)b * Sq;

    int vals[16];
    unsigned long long hist = 0ull;

    #pragma unroll
    for (int i = 0; i < 4; i++) {
        int4 p = xb[t * 4 + i];
        vals[i * 4 + 0] = p.x; vals[i * 4 + 1] = p.y;
        vals[i * 4 + 2] = p.z; vals[i * 4 + 3] = p.w;
        float4 f;
        f.x = score_sm[p.x]; f.y = score_sm[p.y];
        f.z = score_sm[p.z]; f.w = score_sm[p.w];
        ((float4*)fs)[t * 4 + i] = f;
        hist += 1ull << (p.x << 3);
        hist += 1ull << (p.y << 3);
        hist += 1ull << (p.z << 3);
        hist += 1ull << (p.w << 3);
    }
    #pragma unroll
    for (int v = 0; v < Vq; v++) cnt[v][t] = (int)((hist >> (v * 8)) & 0xFF);
    __syncthreads();

    // exclusive scan per token value: warp v scans cnt[v][0..255]
    const int wid = t >> 5, lane = t & 31;
    if (wid < Vq) {
        const int v = wid;
        int loc[8], s = 0;
        #pragma unroll
        for (int i = 0; i < 8; i++) { loc[i] = s; s += cnt[v][lane * 8 + i]; }
        int run = s;
        #pragma unroll
        for (int d = 1; d < 32; d <<= 1) {
            int o = __shfl_up_sync(0xffffffff, run, d);
            if (lane >= d) run += o;
        }
        const int excl = run - s;
        #pragma unroll
        for (int i = 0; i < 8; i++) cnt[v][lane * 8 + i] = excl + loc[i];
        if (lane == 31) tot_sm[v] = run;
    }
    __syncthreads();

    if (t == 0) {
        // stable descending order of the 6 scores (ties -> lower value index)
        int order[Vq];
        bool used[Vq];
        #pragma unroll
        for (int v = 0; v < Vq; v++) used[v] = false;
        #pragma unroll
        for (int g = 0; g < Vq; g++) {
            int best = 0; float bs = -1e30f;
            #pragma unroll
            for (int v = 0; v < Vq; v++)
                if (!used[v] && score_sm[v] > bs) { bs = score_sm[v]; best = v; }
            used[best] = true;
            order[g] = best;
        }
        int rem = Kq, off = 0;
        #pragma unroll
        for (int g = 0; g < Vq; g++) {
            int v = order[g];
            int tk = min(tot_sm[v], rem);
            take_sm[v] = tk; off_sm[v] = off;
            off += tk; rem -= tk;
        }
    }
    __syncthreads();

    // pass 2: compaction into shared, then coalesced global write
    int ctr[Vq];
    #pragma unroll
    for (int v = 0; v < Vq; v++) ctr[v] = cnt[v][t];
    #pragma unroll
    for (int i = 0; i < 16; i++) {
        const int vv = vals[i];
        int rank = 0, tk = 0, off = 0;
        #pragma unroll
        for (int v = 0; v < Vq; v++)
            if (vv == v) { rank = ctr[v]++; tk = take_sm[v]; off = off_sm[v]; }
        if (rank < tk) sh_idx[off + rank] = (float)(t * 16 + i);
    }
    __syncthreads();

    float* oidx = out + Bq + (size_t)b * Kq;
    for (int j = t; j < Kq; j += 256) oidx[j] = sh_idx[j];

    // epilogue: pooled mean over selected attended rows
    if (t < Dq) {
        float s = 0.f;
        #pragma unroll
        for (int v = 0; v < Vq; v++)
            s += (float)take_sm[v] * g_att[v * Dq + t];
        pooled[t] = s * (1.f / (float)Kq);
    }
    __syncthreads();

    // classifier layer 1: 64 neurons x 4 threads (32 inputs each)
    {
        const int n = t >> 2, p = t & 3;
        float s = 0.f;
        const int base = p * 32;
        #pragma unroll 8
        for (int i = 0; i < 32; i++)
            s += pooled[base + i] * C1[(base + i) * 64 + n];
        s += __shfl_xor_sync(0xffffffff, s, 1);
        s += __shfl_xor_sync(0xffffffff, s, 2);
        if (p == 0) hcls[n] = fmaxf(s + c1[n], 0.f);
    }
    __syncthreads();

    // classifier layer 2: one warp reduces 64 values
    if (t < 32) {
        float z = hcls[t] * C2[t] + hcls[t + 32] * C2[t + 32];
        #pragma unroll
        for (int d = 16; d >= 1; d >>= 1) z += __shfl_xor_sync(0xffffffff, z, d);
        if (t == 0) out[b] = 1.f / (1.f + expf(-(z + c2[0])));
    }
}

extern "C" void kernel_launch(void* const* d_in, const int* in_sizes, int n_in,
                              void* d_out, int out_size) {
    const int*   x   = (const int*)d_in[0];
    const float* emb = (const float*)d_in[1];
    const float* W1  = (const float*)d_in[2];
    const float* b1  = (const float*)d_in[3];
    const float* W2  = (const float*)d_in[4];
    const float* b2  = (const float*)d_in[5];
    const float* W3  = (const float*)d_in[6];
    const float* b3  = (const float*)d_in[7];
    const float* A1  = (const float*)d_in[8];
    const float* a1  = (const float*)d_in[9];
    const float* A2  = (const float*)d_in[10];
    const float* a2  = (const float*)d_in[11];
    const float* C1  = (const float*)d_in[12];
    const float* c1  = (const float*)d_in[13];
    const float* C2  = (const float*)d_in[14];
    const float* c2  = (const float*)d_in[15];
    float* out = (float*)d_out;

    precompute_kernel<<<Vq, 128>>>(emb, W1, b1, W2, b2, W3, b3, A1, a1, A2, a2);
    main_kernel<<<Bq, 256>>>(x, C1, c1, C2, c2, out);
}